// round 7
// baseline (speedup 1.0000x reference)
#include <cuda_runtime.h>

// TemporalScaledDotProductforCrossAttention — GB300 fused kernel, v2.
// One CTA per (b,h,n) site. 2 compute warps; each half-warp owns one variant;
// each lane owns TWO q-rows (g=2) so every B/V LDS chunk feeds 2 rows.
//   warp 0: lanes 0-11 -> ff (A=Qf,B=Kf,V=Vf), lanes 12-23 -> fs (A=Kf,B=Qfs,V=Vf)
//   warp 1: lanes 0-11 -> sf (A=Ks,B=Qf,V=Vs), lanes 12-23 -> ss (A=Qs,B=Ks,V=Vs)
// Packed fma.rn.f32x2 halves FMA issue. Tile bases shimmed so the 4 concurrent
// B-read address groups hit distinct bank quadrants (1 wavefront per LDS).

static constexpr int STR4 = 17;    // padded float4 stride per 12-row tile
// tile bases (float4): 204 per tile, +2 shim after tile 3 for bank spreading
__device__ __forceinline__ constexpr int TB(int t) { return t * 204 + (t >= 4 ? 2 : 0); }
static constexpr int SMEM_F4 = 6 * 204 + 2 + 204;   // TB(6) + 204 = 1430

__device__ __forceinline__ unsigned long long fma2(unsigned long long a,
                                                   unsigned long long b,
                                                   unsigned long long c) {
    unsigned long long d;
    asm("fma.rn.f32x2 %0, %1, %2, %3;" : "=l"(d) : "l"(a), "l"(b), "l"(c));
    return d;
}
__device__ __forceinline__ unsigned long long pack2(float x, float y) {
    unsigned long long r;
    asm("mov.b64 %0, {%1, %2};" : "=l"(r) : "f"(x), "f"(y));
    return r;
}
__device__ __forceinline__ float2 unpack2(unsigned long long v) {
    float2 r;
    asm("mov.b64 {%0, %1}, %2;" : "=f"(r.x), "=f"(r.y) : "l"(v));
    return r;
}

__global__ __launch_bounds__(128)
void tsdp_kernel(const float* __restrict__ Qf, const float* __restrict__ Kf,
                 const float* __restrict__ Vf, const float* __restrict__ Qs,
                 const float* __restrict__ Ks, const float* __restrict__ Vs,
                 const float* __restrict__ Kj, const float* __restrict__ Vfp,
                 const int* __restrict__ mask, float* __restrict__ out,
                 int nsite)
{
    // tiles: 0=Qf 1=Kf 2=Vf 3=Qs 4=Ks 5=Vs 6=Qfs(flow-speed)
    __shared__ float4 T[SMEM_F4];
    __shared__ int smask[144];

    const int site = blockIdx.x;
    const int tid  = threadIdx.x;

    // ---- Stage: gmem -> smem (coalesced float4), fuse flow-speed transform ----
    {
        const long long base = (long long)site * 192;
        const float4* gQf = (const float4*)Qf + base;
        const float4* gKf = (const float4*)Kf + base;
        const float4* gVf = (const float4*)Vf + base;
        const float4* gQs = (const float4*)Qs + base;
        const float4* gKs = (const float4*)Ks + base;
        const float4* gVs = (const float4*)Vs + base;

        #pragma unroll
        for (int rep = 0; rep < 2; rep++) {
            int f = tid + rep * 128;
            if (f < 192) {
                int r = f >> 4, c = f & 15;
                int idx = r * STR4 + c;
                T[TB(0) + idx] = gQf[f];
                T[TB(1) + idx] = gKf[f];
                T[TB(2) + idx] = gVf[f];
                float4 v = gQs[f];
                T[TB(3) + idx] = v;
                T[TB(4) + idx] = gKs[f];
                T[TB(5) + idx] = gVs[f];
                // Qfs[k][d] = Kj[k] * (x - x*x / (Vfp[k] + 1e-5))
                float kj    = __ldg(Kj + r);
                float denom = __ldg(Vfp + r) + 1e-5f;
                float4 w;
                w.x = kj * (v.x - (v.x * v.x) / denom);
                w.y = kj * (v.y - (v.y * v.y) / denom);
                w.z = kj * (v.z - (v.z * v.z) / denom);
                w.w = kj * (v.w - (v.w * v.w) / denom);
                T[TB(6) + idx] = w;
            }
        }
    }
    // cover ALL 144 mask entries (strided — R6 fix)
    for (int i = tid; i < 144; i += 128) smask[i] = mask[i];
    __syncthreads();

    const int warp = tid >> 5;
    const int lane = tid & 31;
    if (warp >= 2 || lane >= 24) return;    // warps 2,3 staged and exit

    const int sub = (lane >= 12) ? 1 : 0;   // which variant in this warp
    const int l   = lane - 12 * sub;
    const int qp  = l >> 1;                 // q-pair index 0..5
    const int h   = l & 1;                  // D-half
    const int q0  = 2 * qp, q1 = q0 + 1;
    const int rot = 4 * h;                  // bank rotation

    // operand tiles + output quarter per (warp, sub)
    int aT, bT, vT, outq;
    if (warp == 0) {
        if (!sub) { aT = 0; bT = 1; vT = 2; outq = 0; }   // ff
        else      { aT = 1; bT = 6; vT = 2; outq = 1; }   // fs
    } else {
        if (!sub) { aT = 4; bT = 0; vT = 5; outq = 2; }   // sf
        else      { aT = 3; bT = 4; vT = 5; outq = 3; }   // ss
    }
    const ulonglong2* A2 = (const ulonglong2*)(T + TB(aT));
    const ulonglong2* B2 = (const ulonglong2*)(T + TB(bT));
    const ulonglong2* V2 = (const ulonglong2*)(T + TB(vT));

    // ---- Load both A rows (this h-half, rotated order) into registers ----
    ulonglong2 a0[8], a1[8];
    #pragma unroll
    for (int i = 0; i < 8; i++) {
        int j = (i + rot) & 7;
        a0[i] = A2[q0 * STR4 + h * 8 + j];
        a1[i] = A2[q1 * STR4 + h * 8 + j];
    }

    // ---- Scores: each B chunk feeds both q-rows ----
    float s0[12], s1[12];
    #pragma unroll
    for (int k = 0; k < 12; k++) {
        unsigned long long acc0 = 0ULL, acc1 = 0ULL;
        #pragma unroll
        for (int i = 0; i < 8; i++) {
            ulonglong2 b = B2[k * STR4 + h * 8 + ((i + rot) & 7)];
            acc0 = fma2(a0[i].x, b.x, acc0);
            acc0 = fma2(a0[i].y, b.y, acc0);
            acc1 = fma2(a1[i].x, b.x, acc1);
            acc1 = fma2(a1[i].y, b.y, acc1);
        }
        float2 p0 = unpack2(acc0), p1 = unpack2(acc1);
        s0[k] = p0.x + p0.y;
        s1[k] = p1.x + p1.y;
    }

    // cross-half reduce + scale + exact mask select
    #pragma unroll
    for (int k = 0; k < 12; k++) {
        float v0 = s0[k] + __shfl_xor_sync(0x00ffffffu, s0[k], 1);
        float v1 = s1[k] + __shfl_xor_sync(0x00ffffffu, s1[k], 1);
        s0[k] = (smask[q0 * 12 + k] == 1) ? -1e9f : v0 * 0.125f;
        s1[k] = (smask[q1 * 12 + k] == 1) ? -1e9f : v1 * 0.125f;
    }

    // ---- Softmax per row (both h-lanes redundantly) ----
    float mx0 = s0[0], mx1 = s1[0];
    #pragma unroll
    for (int k = 1; k < 12; k++) { mx0 = fmaxf(mx0, s0[k]); mx1 = fmaxf(mx1, s1[k]); }
    float sum0 = 0.f, sum1 = 0.f;
    #pragma unroll
    for (int k = 0; k < 12; k++) {
        s0[k] = __expf(s0[k] - mx0); sum0 += s0[k];
        s1[k] = __expf(s1[k] - mx1); sum1 += s1[k];
    }
    const float rs0 = 1.0f / sum0, rs1 = 1.0f / sum1;

    // ---- Output: each V chunk feeds both q-rows ----
    ulonglong2 c0[8], c1[8];
    #pragma unroll
    for (int i = 0; i < 8; i++) { c0[i].x = c0[i].y = 0ULL; c1[i].x = c1[i].y = 0ULL; }

    #pragma unroll
    for (int k = 0; k < 12; k++) {
        float z0 = s0[k] * rs0, z1 = s1[k] * rs1;
        unsigned long long z0p = pack2(z0, z0);
        unsigned long long z1p = pack2(z1, z1);
        #pragma unroll
        for (int i = 0; i < 8; i++) {
            ulonglong2 v = V2[k * STR4 + h * 8 + ((i + rot) & 7)];
            c0[i].x = fma2(z0p, v.x, c0[i].x);
            c0[i].y = fma2(z0p, v.y, c0[i].y);
            c1[i].x = fma2(z1p, v.x, c1[i].x);
            c1[i].y = fma2(z1p, v.y, c1[i].y);
        }
    }

    // ---- Store both rows (un-rotate) ----
    float4* ob = (float4*)out + ((long long)outq * nsite + site) * 192 + h * 8;
    float4* o0 = ob + q0 * 16;
    float4* o1 = ob + q1 * 16;
    #pragma unroll
    for (int i = 0; i < 8; i++) {
        int j = (i + rot) & 7;
        float2 lo0 = unpack2(c0[i].x), hi0 = unpack2(c0[i].y);
        float2 lo1 = unpack2(c1[i].x), hi1 = unpack2(c1[i].y);
        o0[j] = make_float4(lo0.x, lo0.y, hi0.x, hi0.y);
        o1[j] = make_float4(lo1.x, lo1.y, hi1.x, hi1.y);
    }
}

extern "C" void kernel_launch(void* const* d_in, const int* in_sizes, int n_in,
                              void* d_out, int out_size) {
    const int nsite = in_sizes[0] / 768;   // B*H*L1 = 39296
    tsdp_kernel<<<nsite, 128>>>(
        (const float*)d_in[0], (const float*)d_in[1], (const float*)d_in[2],
        (const float*)d_in[3], (const float*)d_in[4], (const float*)d_in[5],
        (const float*)d_in[6], (const float*)d_in[7],
        (const int*)d_in[8],
        (float*)d_out, nsite);
}

// round 8
// speedup vs baseline: 1.3220x; 1.3220x over previous
#include <cuda_runtime.h>

// TemporalScaledDotProductforCrossAttention — GB300 fused kernel, v3.
// TWO sites per CTA; warps 0,1 -> site A, warps 2,3 -> site B (all 4 SMSPs busy).
// Each warp packs 2 variants in half-warps (pair 0: ff+fs, pair 1: sf+ss);
// each lane owns TWO q-rows (g=2) so every B/V LDS chunk feeds 2 rows
//   -> per-site B and V shared-memory instruction counts are HALF of R6.
// Packed fma.rn.f32x2 halves FMA issue. A-hoist chunked (4 f4 per row live)
// to keep regs ~110; __launch_bounds__(128,4) caps at 128 regs -> 4 CTAs/SM.

static constexpr int STR4 = 17;    // padded float4 stride per 12-row tile
// tile bases (float4): 204 per tile, +2 shim after tile 3 for bank spreading
__device__ __forceinline__ constexpr int TB(int t) { return t * 204 + (t >= 4 ? 2 : 0); }
static constexpr int SITE_F4 = 6 * 204 + 2 + 204;   // 1430 float4 per site

__device__ __forceinline__ unsigned long long fma2(unsigned long long a,
                                                   unsigned long long b,
                                                   unsigned long long c) {
    unsigned long long d;
    asm("fma.rn.f32x2 %0, %1, %2, %3;" : "=l"(d) : "l"(a), "l"(b), "l"(c));
    return d;
}
__device__ __forceinline__ unsigned long long pack2(float x, float y) {
    unsigned long long r;
    asm("mov.b64 %0, {%1, %2};" : "=l"(r) : "f"(x), "f"(y));
    return r;
}
__device__ __forceinline__ float2 unpack2(unsigned long long v) {
    float2 r;
    asm("mov.b64 {%0, %1}, %2;" : "=f"(r.x), "=f"(r.y) : "l"(v));
    return r;
}

__global__ __launch_bounds__(128, 4)
void tsdp_kernel(const float* __restrict__ Qf, const float* __restrict__ Kf,
                 const float* __restrict__ Vf, const float* __restrict__ Qs,
                 const float* __restrict__ Ks, const float* __restrict__ Vs,
                 const float* __restrict__ Kj, const float* __restrict__ Vfp,
                 const int* __restrict__ mask, float* __restrict__ out,
                 int nsite)
{
    // tiles per site: 0=Qf 1=Kf 2=Vf 3=Qs 4=Ks 5=Vs 6=Qfs(flow-speed)
    __shared__ float4 T[2 * SITE_F4];
    __shared__ int smask[144];

    const int site0 = blockIdx.x * 2;
    const int tid   = threadIdx.x;

    // ---- Stage BOTH sites: gmem -> smem (coalesced float4) ----
    #pragma unroll
    for (int rep = 0; rep < 3; rep++) {
        int f  = tid + rep * 128;              // [0, 384)
        int sl = (f >= 192) ? 1 : 0;
        int fl = f - 192 * sl;
        int r  = fl >> 4, c = fl & 15;
        int idx = sl * SITE_F4 + r * STR4 + c;
        long long g = (long long)(site0 + sl) * 192 + fl;

        T[TB(0) + idx] = ((const float4*)Qf)[g];
        T[TB(1) + idx] = ((const float4*)Kf)[g];
        T[TB(2) + idx] = ((const float4*)Vf)[g];
        float4 v = ((const float4*)Qs)[g];
        T[TB(3) + idx] = v;
        T[TB(4) + idx] = ((const float4*)Ks)[g];
        T[TB(5) + idx] = ((const float4*)Vs)[g];
        // Qfs[k][d] = Kj[k] * (x - x*x / (Vfp[k] + 1e-5))
        float kj    = __ldg(Kj + r);
        float denom = __ldg(Vfp + r) + 1e-5f;
        float4 w;
        w.x = kj * (v.x - (v.x * v.x) / denom);
        w.y = kj * (v.y - (v.y * v.y) / denom);
        w.z = kj * (v.z - (v.z * v.z) / denom);
        w.w = kj * (v.w - (v.w * v.w) / denom);
        T[TB(6) + idx] = w;
    }
    // mask shared across sites; cover all 144 entries
    for (int i = tid; i < 144; i += 128) smask[i] = mask[i];
    __syncthreads();

    const int warp = tid >> 5;
    const int lane = tid & 31;
    if (lane >= 24) return;                  // no further block syncs

    const int siteLoc = warp >> 1;           // 0 or 1
    const int pairId  = warp & 1;            // 0: ff+fs, 1: sf+ss
    const int site    = site0 + siteLoc;

    const int sub = (lane >= 12) ? 1 : 0;    // variant within the pair
    const int l   = lane - 12 * sub;
    const int qp  = l >> 1;                  // q-pair 0..5
    const int h   = l & 1;                   // D-half
    const int q0  = 2 * qp, q1 = q0 + 1;
    const int rot = 4 * h;

    // operand tiles + output quarter per (pairId, sub)
    int aT, bT, vT, outq;
    if (pairId == 0) {
        if (!sub) { aT = 0; bT = 1; vT = 2; outq = 0; }   // ff: Qf·Kf^T  -> Vf
        else      { aT = 1; bT = 6; vT = 2; outq = 1; }   // fs: Kf·Qfs^T -> Vf
    } else {
        if (!sub) { aT = 4; bT = 0; vT = 5; outq = 2; }   // sf: Ks·Qf^T  -> Vs
        else      { aT = 3; bT = 4; vT = 5; outq = 3; }   // ss: Qs·Ks^T  -> Vs
    }
    const float4* Ts = T + siteLoc * SITE_F4;
    const ulonglong2* A2 = (const ulonglong2*)(Ts + TB(aT));
    const ulonglong2* B2 = (const ulonglong2*)(Ts + TB(bT));
    const ulonglong2* V2 = (const ulonglong2*)(Ts + TB(vT));

    // ---- Scores: each B chunk feeds both q-rows; chunked A hoist (low regs) ----
    float s0[12], s1[12];
    #pragma unroll
    for (int k = 0; k < 12; k++) { s0[k] = 0.0f; s1[k] = 0.0f; }

    #pragma unroll
    for (int ch = 0; ch < 2; ch++) {
        ulonglong2 a0[4], a1[4];
        int jj[4];
        #pragma unroll
        for (int i = 0; i < 4; i++) {
            jj[i] = (ch * 4 + i + rot) & 7;
            a0[i] = A2[q0 * STR4 + h * 8 + jj[i]];
            a1[i] = A2[q1 * STR4 + h * 8 + jj[i]];
        }
        #pragma unroll
        for (int k = 0; k < 12; k++) {
            unsigned long long acc0 = 0ULL, acc1 = 0ULL;
            #pragma unroll
            for (int i = 0; i < 4; i++) {
                ulonglong2 b = B2[k * STR4 + h * 8 + jj[i]];
                acc0 = fma2(a0[i].x, b.x, acc0);
                acc0 = fma2(a0[i].y, b.y, acc0);
                acc1 = fma2(a1[i].x, b.x, acc1);
                acc1 = fma2(a1[i].y, b.y, acc1);
            }
            float2 p0 = unpack2(acc0), p1 = unpack2(acc1);
            s0[k] += p0.x + p0.y;
            s1[k] += p1.x + p1.y;
        }
    }

    // cross-half reduce + scale + exact mask select
    #pragma unroll
    for (int k = 0; k < 12; k++) {
        float v0 = s0[k] + __shfl_xor_sync(0x00ffffffu, s0[k], 1);
        float v1 = s1[k] + __shfl_xor_sync(0x00ffffffu, s1[k], 1);
        s0[k] = (smask[q0 * 12 + k] == 1) ? -1e9f : v0 * 0.125f;
        s1[k] = (smask[q1 * 12 + k] == 1) ? -1e9f : v1 * 0.125f;
    }

    // ---- Softmax per row (both h-lanes redundantly) ----
    float mx0 = s0[0], mx1 = s1[0];
    #pragma unroll
    for (int k = 1; k < 12; k++) { mx0 = fmaxf(mx0, s0[k]); mx1 = fmaxf(mx1, s1[k]); }
    float sum0 = 0.f, sum1 = 0.f;
    #pragma unroll
    for (int k = 0; k < 12; k++) {
        s0[k] = __expf(s0[k] - mx0); sum0 += s0[k];
        s1[k] = __expf(s1[k] - mx1); sum1 += s1[k];
    }
    const float rs0 = 1.0f / sum0, rs1 = 1.0f / sum1;

    // ---- Output: each V chunk feeds both q-rows (addresses shared across subs) ----
    ulonglong2 c0[8], c1[8];
    #pragma unroll
    for (int i = 0; i < 8; i++) { c0[i].x = c0[i].y = 0ULL; c1[i].x = c1[i].y = 0ULL; }

    #pragma unroll
    for (int k = 0; k < 12; k++) {
        float z0 = s0[k] * rs0, z1 = s1[k] * rs1;
        unsigned long long z0p = pack2(z0, z0);
        unsigned long long z1p = pack2(z1, z1);
        #pragma unroll
        for (int i = 0; i < 8; i++) {
            ulonglong2 v = V2[k * STR4 + h * 8 + ((i + rot) & 7)];
            c0[i].x = fma2(z0p, v.x, c0[i].x);
            c0[i].y = fma2(z0p, v.y, c0[i].y);
            c1[i].x = fma2(z1p, v.x, c1[i].x);
            c1[i].y = fma2(z1p, v.y, c1[i].y);
        }
    }

    // ---- Store both rows (un-rotate); quarters ordered (ff, fs, sf, ss) ----
    float4* ob = (float4*)out + ((long long)outq * nsite + site) * 192 + h * 8;
    float4* o0 = ob + q0 * 16;
    float4* o1 = ob + q1 * 16;
    #pragma unroll
    for (int i = 0; i < 8; i++) {
        int j = (i + rot) & 7;
        float2 lo0 = unpack2(c0[i].x), hi0 = unpack2(c0[i].y);
        float2 lo1 = unpack2(c1[i].x), hi1 = unpack2(c1[i].y);
        o0[j] = make_float4(lo0.x, lo0.y, hi0.x, hi0.y);
        o1[j] = make_float4(lo1.x, lo1.y, hi1.x, hi1.y);
    }
}

extern "C" void kernel_launch(void* const* d_in, const int* in_sizes, int n_in,
                              void* d_out, int out_size) {
    const int nsite = in_sizes[0] / 768;   // B*H*L1 = 39296 (even)
    tsdp_kernel<<<nsite / 2, 128>>>(
        (const float*)d_in[0], (const float*)d_in[1], (const float*)d_in[2],
        (const float*)d_in[3], (const float*)d_in[4], (const float*)d_in[5],
        (const float*)d_in[6], (const float*)d_in[7],
        (const int*)d_in[8],
        (float*)d_out, nsite);
}